// round 1
// baseline (speedup 1.0000x reference)
#include <cuda_runtime.h>
#include <cstdint>

// ---------------------------------------------------------------------------
// AnchorLayer: B=16, A=12, H=W=64 (N=49152 anchors/row), G=64 gt boxes.
// Output (B, A, H, W, 5) = [label, tx, ty, tw, th], float32.
//
// Stages:
//   k_init  : zero counters/histograms, set sentinels
//   k_main  : keep-mask, IoU max/argmax over 64 gt, labels, targets,
//             threefry key (23-bit), per-row hist over key top-12 bits,
//             global pos/neg counts
//   k_scan1 : per-row descending scan of hist1 -> threshold bin T1, count C1
//   k_hist2 : per-row hist over low-11 bits of keys in bin T1
//   k_scan2 : per-row descending scan of hist2 -> exact threshold key K*
//   k_final : negatives with key < K* -> label -1; key == K*: index-rank tiebreak
// ---------------------------------------------------------------------------

#define BB   16
#define NN   49152          // anchors per batch row
#define GG   64
#define TOT  (BB * NN)      // 786432
#define HALF (TOT / 2)      // 393216 (only used by non-partitionable path)
#define SENT 0xFFFFFFFFu

// JAX default PRNG scheme. 1 = threefry_partitionable (modern JAX default):
// bits[i] = o0 ^ o1 of threefry2x32(key, (0, i)).
// 0 = original: counters split in halves, take o0 for first half, o1 second.
#define TF_PARTITIONABLE 1

__device__ unsigned g_pos, g_neg;
__device__ unsigned g_hist1[BB * 4096];
__device__ unsigned g_hist2[BB * 2048];
__device__ unsigned g_T1[BB], g_C1[BB];
__device__ unsigned g_T2[BB], g_C2[BB];
__device__ unsigned g_key[TOT];   // key23 for negatives, SENT otherwise

// ---------------- threefry-2x32, key = (0, 42) -----------------------------
__device__ __forceinline__ unsigned tf_rotl(unsigned x, int d) {
    return (x << d) | (x >> (32 - d));
}

__device__ __forceinline__ unsigned rand_bits(unsigned i) {
    const unsigned ks0 = 0u, ks1 = 42u, ks2 = 0x1BD11BDAu ^ 0u ^ 42u;
#if TF_PARTITIONABLE
    unsigned x0 = 0u, x1 = i;
#else
    bool lo = i < HALF;
    unsigned x0 = lo ? i : i - HALF;
    unsigned x1 = lo ? i + HALF : i;
#endif
    x0 += ks0; x1 += ks1;
#define TF_R(r) { x0 += x1; x1 = tf_rotl(x1, r); x1 ^= x0; }
    TF_R(13) TF_R(15) TF_R(26) TF_R(6)
    x0 += ks1; x1 += ks2 + 1u;
    TF_R(17) TF_R(29) TF_R(16) TF_R(24)
    x0 += ks2; x1 += ks0 + 2u;
    TF_R(13) TF_R(15) TF_R(26) TF_R(6)
    x0 += ks0; x1 += ks1 + 3u;
    TF_R(17) TF_R(29) TF_R(16) TF_R(24)
    x0 += ks1; x1 += ks2 + 4u;
    TF_R(13) TF_R(15) TF_R(26) TF_R(6)
    x0 += ks2; x1 += ks0 + 5u;
#undef TF_R
#if TF_PARTITIONABLE
    return x0 ^ x1;
#else
    return lo ? x0 : x1;
#endif
}

// ---------------- init -----------------------------------------------------
__global__ void k_init() {
    int idx = blockIdx.x * blockDim.x + threadIdx.x;
    if (idx < BB * 4096) g_hist1[idx] = 0u;
    if (idx < BB * 2048) g_hist2[idx] = 0u;
    if (idx < BB) {
        g_T1[idx] = SENT; g_C1[idx] = 0u;
        g_T2[idx] = 0u;   g_C2[idx] = 0u;
    }
    if (idx == 0) { g_pos = 0u; g_neg = 0u; }
}

// ---------------- main: IoU + labels + targets + keys ----------------------
__global__ void __launch_bounds__(256) k_main(
    const float4* __restrict__ anchors,   // N float4 (x0,y0,w,h)
    const float4* __restrict__ gt,        // B*G float4 (x,y,w,h)
    float* __restrict__ out)
{
    __shared__ float4 s_box[GG];    // gx0, gy0, gx1, gy1 for this batch
    __shared__ float  s_area[GG];
    __shared__ float4 s_gt0[GG];    // batch-0 raw gt (targets use gt_flat[argmax])
    const int b = blockIdx.y;
    const int t = threadIdx.x;
    const int j = blockIdx.x * 256 + t;

    if (t < GG) {
        float4 gb = gt[b * GG + t];
        s_box[t]  = make_float4(gb.x, gb.y, __fadd_rn(gb.x, gb.z), __fadd_rn(gb.y, gb.w));
        s_area[t] = __fmul_rn(gb.z, gb.w);
        s_gt0[t]  = gt[t];
    }
    __syncthreads();

    float4 a = anchors[j];
    const float ax0 = a.x, ay0 = a.y, aw = a.z, ah = a.w;
    const float ax1 = __fadd_rn(ax0, aw);
    const float ay1 = __fadd_rn(ay0, ah);
    const float aArea = __fmul_rn(aw, ah);
    const float kx1 = __fsub_rn(ax1, 1.0f);
    const float ky1 = __fsub_rn(ay1, 1.0f);
    const bool keep = (ax0 >= 0.0f) && (ay0 >= 0.0f) && (aw >= 0.0f) && (ah >= 0.0f)
                   && (ax0 <= 63.0f) && (ay0 <= 63.0f) && (kx1 <= 63.0f) && (ky1 <= 63.0f);

    float best = -1.0f;
    int   barg = 0;
    if (keep) {
#pragma unroll 8
        for (int g = 0; g < GG; g++) {
            float4 gb = s_box[g];
            float iw = fmaxf(0.0f, __fsub_rn(fminf(ax1, gb.z), fmaxf(ax0, gb.x)));
            float ih = fmaxf(0.0f, __fsub_rn(fminf(ay1, gb.w), fmaxf(ay0, gb.y)));
            float inter = __fmul_rn(iw, ih);
            float ov;
            if (inter > 0.0f) {
                float uni = __fsub_rn(__fadd_rn(aArea, s_area[g]), inter);
                ov = __fdiv_rn(inter, uni);
                if (ov == 0.0f) ov = 1e-10f;    // faithful to where(ov==0, 1e-10)
            } else {
                ov = 1e-10f;
            }
            if (ov > best) { best = ov; barg = g; }   // first-occurrence argmax
        }
    }

    float lab;
    if (!keep)                  lab = -1.0f;
    else if (best >= 0.7f)      lab =  1.0f;
    else if (best <= 0.3f)      lab =  0.0f;
    else                        lab = -1.0f;

    const bool ispos = keep && (best > 0.7f);
    const bool isneg = keep && (best < 0.3f);
    unsigned bp = __ballot_sync(0xffffffffu, ispos);
    unsigned bn = __ballot_sync(0xffffffffu, isneg);
    if ((t & 31) == 0) {
        if (bp) atomicAdd(&g_pos, (unsigned)__popc(bp));
        if (bn) atomicAdd(&g_neg, (unsigned)__popc(bn));
    }

    const unsigned i = (unsigned)b * NN + (unsigned)j;
    unsigned key = SENT;
    if (lab == 0.0f) {
        key = rand_bits(i) >> 9;                      // 23-bit mantissa key
        atomicAdd(&g_hist1[b * 4096 + (key >> 11)], 1u);
    }
    g_key[i] = key;

    const size_t o = (size_t)i * 5;
    out[o] = lab;
    if (keep) {
        float4 g0 = s_gt0[barg];                      // reference uses batch-0 gt!
        out[o + 1] = __fsub_rn(ax0, __fmul_rn(g0.x, 0.0625f));
        out[o + 2] = __fsub_rn(ay0, __fmul_rn(g0.y, 0.0625f));
        out[o + 3] = __fsub_rn(aw,  __fmul_rn(g0.z, 0.0625f));
        out[o + 4] = __fsub_rn(ah,  __fmul_rn(g0.w, 0.0625f));
    } else {
        out[o + 1] = 0.0f; out[o + 2] = 0.0f; out[o + 3] = 0.0f; out[o + 4] = 0.0f;
    }
}

// ------------- block-wide descending cumulative select (1024 threads) ------
template <int NB>
__device__ void block_select(const unsigned* __restrict__ hist, unsigned target,
                             unsigned* out_bin, unsigned* out_before)
{
    constexpr int IT = NB / 1024;
    const int t = threadIdx.x, lane = t & 31, wid = t >> 5;
    unsigned v[IT];
    unsigned s = 0u;
#pragma unroll
    for (int q = 0; q < IT; q++) { v[q] = hist[NB - 1 - (t * IT + q)]; s += v[q]; }
    unsigned inc = s;
#pragma unroll
    for (int o = 1; o < 32; o <<= 1) {
        unsigned u = __shfl_up_sync(0xffffffffu, inc, o);
        if (lane >= o) inc += u;
    }
    __shared__ unsigned sw[32];
    if (lane == 31) sw[wid] = inc;
    __syncthreads();
    if (wid == 0) {
        unsigned w = sw[lane];
#pragma unroll
        for (int o = 1; o < 32; o <<= 1) {
            unsigned u = __shfl_up_sync(0xffffffffu, w, o);
            if (lane >= o) w += u;
        }
        sw[lane] = w;
    }
    __syncthreads();
    unsigned c = inc - s + (wid > 0 ? sw[wid - 1] : 0u);   // exclusive prefix
#pragma unroll
    for (int q = 0; q < IT; q++) {
        unsigned c2 = c + v[q];
        if (c < target && target <= c2) {
            *out_bin = (unsigned)(NB - 1 - (t * IT + q));
            *out_before = c;
        }
        c = c2;
    }
}

__device__ __forceinline__ unsigned cutoff_val() {
    unsigned c = 3u * g_pos;
    return c < 1u ? 1u : c;
}

__global__ void k_scan1() {
    const int b = blockIdx.x;
    const unsigned cutoff = cutoff_val();
    if (g_neg <= cutoff) return;                 // global gate: no disable at all
    block_select<4096>(g_hist1 + b * 4096, cutoff, &g_T1[b], &g_C1[b]);
}

__global__ void k_hist2() {
    const int b = blockIdx.y;
    const int j = blockIdx.x * 256 + threadIdx.x;
    const unsigned key = g_key[(unsigned)b * NN + j];
    if (key == SENT) return;
    if ((key >> 11) == g_T1[b])
        atomicAdd(&g_hist2[b * 2048 + (key & 2047u)], 1u);
}

__global__ void k_scan2() {
    const int b = blockIdx.x;
    const unsigned t1 = g_T1[b];
    if (t1 == SENT) return;                      // no disable in this row
    const unsigned target = cutoff_val() - g_C1[b];   // >= 1 by construction
    block_select<2048>(g_hist2 + b * 2048, target, &g_T2[b], &g_C2[b]);
}

__global__ void k_final(float* __restrict__ out) {
    const int b = blockIdx.y;
    const int j = blockIdx.x * 256 + threadIdx.x;
    const unsigned i = (unsigned)b * NN + (unsigned)j;
    const unsigned key = g_key[i];
    if (key == SENT) return;                     // not a label-0 negative
    const unsigned t1 = g_T1[b];
    if (t1 == SENT) return;                      // row survives entirely
    const unsigned Ks = (t1 << 11) | g_T2[b];
    if (key > Ks) return;                        // rank < cutoff: survives
    if (key < Ks) { out[(size_t)i * 5] = -1.0f; return; }
    // key == K*: survive only the m lowest-index ties
    const unsigned m = cutoff_val() - g_C1[b] - g_C2[b];
    const unsigned* row = g_key + (size_t)b * NN;
    unsigned cnt = 0u;
    for (int jj = 0; jj < j; jj++) cnt += (row[jj] == Ks);
    if (cnt >= m) out[(size_t)i * 5] = -1.0f;
}

// ---------------------------------------------------------------------------
extern "C" void kernel_launch(void* const* d_in, const int* in_sizes, int n_in,
                              void* d_out, int out_size)
{
    (void)in_sizes; (void)n_in; (void)out_size;
    const float4* gt      = (const float4*)d_in[1];   // (16, 64, 4)
    const float4* anchors = (const float4*)d_in[2];   // (12, 64, 64, 4) -> N float4
    float* out = (float*)d_out;

    dim3 gridBN(NN / 256, BB);
    k_init <<<256, 256>>>();
    k_main <<<gridBN, 256>>>(anchors, gt, out);
    k_scan1<<<BB, 1024>>>();
    k_hist2<<<gridBN, 256>>>();
    k_scan2<<<BB, 1024>>>();
    k_final<<<gridBN, 256>>>(out);
}